// round 1
// baseline (speedup 1.0000x reference)
#include <cuda_runtime.h>

#define RES    512
#define FEAT   32
#define NPLANE 6

// Channel-last scratch: [6][512][512][32] floats = 201.3 MB (static __device__,
// allowed by harness rules; no runtime allocation).
__device__ float g_scratch[(size_t)NPLANE * RES * RES * FEAT];

// ---------------------------------------------------------------------------
// Transpose [p][c][h][w] -> [p][h][w][c], smem-tiled so both the global read
// (contiguous in w) and the global write (contiguous in c) are coalesced.
// Block = (32,32): tx,ty. Each block handles one (p, h, w-tile of 32), all 32 c.
// ---------------------------------------------------------------------------
__global__ void transpose_planes_kernel(const float* __restrict__ planes) {
    __shared__ float tile[32][33];

    const int wt = blockIdx.x;   // w tile: 0..15
    const int h  = blockIdx.y;   // 0..511
    const int p  = blockIdx.z;   // 0..5
    const int tx = threadIdx.x;
    const int ty = threadIdx.y;

    // read planes[p][c=ty][h][w = wt*32+tx]  (coalesced in tx)
    const size_t rd = (((size_t)p * FEAT + ty) * RES + h) * RES + (wt * 32 + tx);
    tile[ty][tx] = planes[rd];
    __syncthreads();

    // write scratch[p][h][w = wt*32+ty][c = tx]  (coalesced in tx)
    const size_t wr = ((((size_t)p * RES + h) * RES) + (wt * 32 + ty)) * FEAT + tx;
    g_scratch[wr] = tile[tx][ty];
}

// ---------------------------------------------------------------------------
// Bilinear sample of one plane for channel `lane`. Coordinates follow the
// reference exactly: x = clip((cx+1)*0.5*(W-1), 0, W-1), border padding,
// align_corners=True.
// ---------------------------------------------------------------------------
__device__ __forceinline__ float sample_plane(int p, float cx, float cy, int lane) {
    const float x = fminf(fmaxf((cx + 1.0f) * 0.5f * (float)(RES - 1), 0.0f), (float)(RES - 1));
    const float y = fminf(fmaxf((cy + 1.0f) * 0.5f * (float)(RES - 1), 0.0f), (float)(RES - 1));

    const float x0f = floorf(x);
    const float y0f = floorf(y);
    const int x0 = (int)x0f;
    const int y0 = (int)y0f;
    const int x1 = min(x0 + 1, RES - 1);
    const int y1 = min(y0 + 1, RES - 1);
    const float wx = x - x0f;
    const float wy = y - y0f;

    const float* __restrict__ base = g_scratch + (size_t)p * RES * RES * FEAT;
    const float* __restrict__ r0 = base + (size_t)y0 * RES * FEAT;
    const float* __restrict__ r1 = base + (size_t)y1 * RES * FEAT;

    const float v00 = __ldg(r0 + x0 * FEAT + lane);
    const float v01 = __ldg(r0 + x1 * FEAT + lane);
    const float v10 = __ldg(r1 + x0 * FEAT + lane);
    const float v11 = __ldg(r1 + x1 * FEAT + lane);

    return v00 * ((1.0f - wx) * (1.0f - wy))
         + v01 * (wx * (1.0f - wy))
         + v10 * ((1.0f - wx) * wy)
         + v11 * (wx * wy);
}

// ---------------------------------------------------------------------------
// One warp per point; lane = channel. Every corner fetch is one coalesced
// 128B warp load from the channel-last scratch.
// ---------------------------------------------------------------------------
__global__ void __launch_bounds__(256)
sample_points_kernel(const float* __restrict__ pts,
                     const float* __restrict__ tim,
                     float* __restrict__ out,
                     int N) {
    const int gtid = blockIdx.x * blockDim.x + threadIdx.x;
    const int pt   = gtid >> 5;
    const int lane = gtid & 31;
    if (pt >= N) return;

    // Normalize: pts_n = (pts - (-B)) / (2B) * 2 - 1 = pts / B, B = 1.6
    const float inv_b = 1.0f / 1.6f;
    const float dx = pts[(size_t)pt * 3 + 0] * inv_b;
    const float dy = pts[(size_t)pt * 3 + 1] * inv_b;
    const float dz = pts[(size_t)pt * 3 + 2] * inv_b;
    const float dt = tim[pt] * 2.0f - 1.0f;

    // idx = [[0,1],[0,2],[3,0],[1,2],[3,1],[3,2]] ; coords[:,0] -> x(W), [:,1] -> y(H)
    const float f0 = sample_plane(0, dx, dy, lane);
    const float f1 = sample_plane(1, dx, dz, lane);
    const float f2 = sample_plane(2, dt, dx, lane);
    const float f3 = sample_plane(3, dy, dz, lane);
    const float f4 = sample_plane(4, dt, dy, lane);
    const float f5 = sample_plane(5, dt, dz, lane);

    const float space     = f0 * f1 * f3;
    const float spacetime = f2 * f4 * f5;

    out[(size_t)pt * FEAT + lane]                     = space;
    out[(size_t)N * FEAT + (size_t)pt * FEAT + lane]  = spacetime;
}

extern "C" void kernel_launch(void* const* d_in, const int* in_sizes, int n_in,
                              void* d_out, int out_size) {
    const float* pts    = (const float*)d_in[0];
    const float* tim    = (const float*)d_in[1];
    const float* planes = (const float*)d_in[2];
    // d_in[3] = scales (int, == 1) : unused

    const int N = in_sizes[0] / 3;

    // 1) channel-last transpose of all 6 planes
    transpose_planes_kernel<<<dim3(RES / 32, RES, NPLANE), dim3(32, 32)>>>(planes);

    // 2) warp-per-point gather + bilinear + products
    const int warps_per_block = 256 / 32;
    const int blocks = (N + warps_per_block - 1) / warps_per_block;
    sample_points_kernel<<<blocks, 256>>>(pts, tim, (float*)d_out, N);
}

// round 2
// speedup vs baseline: 1.2774x; 1.2774x over previous
#include <cuda_runtime.h>
#include <cuda_fp16.h>

#define RES    512
#define FEAT   32
#define NPLANE 6
#define PAIRS  (FEAT / 2)   // 16 half2 per texel

// Channel-last fp16 scratch: [6][512][512][32] halves = 100.7 MB (< 126 MB L2).
__device__ __half2 g_scratch[(size_t)NPLANE * RES * RES * PAIRS];

// ---------------------------------------------------------------------------
// Transpose+convert [p][c][h][w] fp32 -> [p][h][w][c-pairs] half2.
// Block (32,32): read coalesced in w, write coalesced in channel-pair.
// ---------------------------------------------------------------------------
__global__ void transpose_convert_kernel(const float* __restrict__ planes) {
    __shared__ float tile[32][33];

    const int wt = blockIdx.x;   // w tile 0..15
    const int h  = blockIdx.y;   // 0..511
    const int p  = blockIdx.z;   // 0..5
    const int tx = threadIdx.x;
    const int ty = threadIdx.y;

    // read planes[p][c=ty][h][w=wt*32+tx]  (coalesced in tx)
    const size_t rd = (((size_t)p * FEAT + ty) * RES + h) * RES + (wt * 32 + tx);
    tile[ty][tx] = planes[rd];
    __syncthreads();

    // write scratch[p][h][w=wt*32+ty][pair=tx] for tx<16 (coalesced in tx)
    if (tx < PAIRS) {
        const __half2 v = __floats2half2_rn(tile[2 * tx][ty], tile[2 * tx + 1][ty]);
        const int wr = (((p * RES + h) * RES) + (wt * 32 + ty)) * PAIRS + tx;
        g_scratch[wr] = v;
    }
}

// ---------------------------------------------------------------------------
// 16 threads per point; thread `sub` owns channel pair sub (channels 2s,2s+1).
// Each corner fetch: 16 lanes * 4B = 64B contiguous. fp32 interpolation.
// ---------------------------------------------------------------------------
__global__ void __launch_bounds__(256)
sample_points_kernel(const float* __restrict__ pts,
                     const float* __restrict__ tim,
                     float* __restrict__ out,
                     int N) {
    const int g   = blockIdx.x * blockDim.x + threadIdx.x;
    const int pt  = g >> 4;
    const int sub = g & 15;
    if (pt >= N) return;

    const float inv_b = 1.0f / 1.6f;
    const float dx = pts[pt * 3 + 0] * inv_b;
    const float dy = pts[pt * 3 + 1] * inv_b;
    const float dz = pts[pt * 3 + 2] * inv_b;
    const float dt = tim[pt] * 2.0f - 1.0f;

    // idx = [[0,1],[0,2],[3,0],[1,2],[3,1],[3,2]] -> (x=W coord, y=H coord)
    const float cxs[NPLANE] = { dx, dx, dt, dy, dt, dt };
    const float cys[NPLANE] = { dy, dz, dx, dz, dy, dz };

    float fx[NPLANE], fy[NPLANE];   // interpolated feature (2 channels)

    #pragma unroll
    for (int p = 0; p < NPLANE; ++p) {
        const float x = fminf(fmaxf((cxs[p] + 1.0f) * 0.5f * (float)(RES - 1), 0.0f), (float)(RES - 1));
        const float y = fminf(fmaxf((cys[p] + 1.0f) * 0.5f * (float)(RES - 1), 0.0f), (float)(RES - 1));
        const float x0f = floorf(x);
        const float y0f = floorf(y);
        const int x0 = (int)x0f;
        const int y0 = (int)y0f;
        const int x1 = min(x0 + 1, RES - 1);
        const int y1 = min(y0 + 1, RES - 1);
        const float wx = x - x0f;
        const float wy = y - y0f;

        const int pbase = p * (RES * RES * PAIRS);
        const int r0 = pbase + (y0 * RES) * PAIRS + sub;
        const int r1 = pbase + (y1 * RES) * PAIRS + sub;

        const __half2 h00 = __ldg(&g_scratch[r0 + x0 * PAIRS]);
        const __half2 h01 = __ldg(&g_scratch[r0 + x1 * PAIRS]);
        const __half2 h10 = __ldg(&g_scratch[r1 + x0 * PAIRS]);
        const __half2 h11 = __ldg(&g_scratch[r1 + x1 * PAIRS]);

        const float2 v00 = __half22float2(h00);
        const float2 v01 = __half22float2(h01);
        const float2 v10 = __half22float2(h10);
        const float2 v11 = __half22float2(h11);

        const float w00 = (1.0f - wx) * (1.0f - wy);
        const float w01 = wx * (1.0f - wy);
        const float w10 = (1.0f - wx) * wy;
        const float w11 = wx * wy;

        fx[p] = v00.x * w00 + v01.x * w01 + v10.x * w10 + v11.x * w11;
        fy[p] = v00.y * w00 + v01.y * w01 + v10.y * w10 + v11.y * w11;
    }

    const float2 space     = make_float2(fx[0] * fx[1] * fx[3], fy[0] * fy[1] * fy[3]);
    const float2 spacetime = make_float2(fx[2] * fx[4] * fx[5], fy[2] * fy[4] * fy[5]);

    float2* __restrict__ o0 = (float2*)(out) + (size_t)pt * PAIRS + sub;
    float2* __restrict__ o1 = (float2*)(out) + (size_t)N * PAIRS + (size_t)pt * PAIRS + sub;
    *o0 = space;
    *o1 = spacetime;
}

extern "C" void kernel_launch(void* const* d_in, const int* in_sizes, int n_in,
                              void* d_out, int out_size) {
    const float* pts    = (const float*)d_in[0];
    const float* tim    = (const float*)d_in[1];
    const float* planes = (const float*)d_in[2];

    const int N = in_sizes[0] / 3;

    transpose_convert_kernel<<<dim3(RES / 32, RES, NPLANE), dim3(32, 32)>>>(planes);

    const int threads_total = N * 16;
    const int blocks = (threads_total + 255) / 256;
    sample_points_kernel<<<blocks, 256>>>(pts, tim, (float*)d_out, N);
}

// round 4
// speedup vs baseline: 2.2158x; 1.7347x over previous
#include <cuda_runtime.h>
#include <cuda_fp16.h>

#define RES    512
#define FEAT   32
#define NPLANE 6
#define PAIRS  (FEAT / 2)   // 16 half2 per texel

// Channel-last fp16 scratch: [6][512][512][16] half2 = 100.7 MB (< 126 MB L2).
__device__ __half2 g_scratch[(size_t)NPLANE * RES * RES * PAIRS];

// ---------------------------------------------------------------------------
// Transpose+convert [p][c][h][w] fp32 -> [p][h][w][pair] half2.
// Block (32,16) = 512 threads. Load: each thread reads channels ty and ty+16
// (coalesced in w, streaming). Write: each warp (fixed ty) emits one 128B
// contiguous store covering texels wl=2ty,2ty+1 x 16 pairs.
// ---------------------------------------------------------------------------
__global__ void transpose_convert_kernel(const float* __restrict__ planes) {
    __shared__ float tile[32][33];   // [channel][w]

    const int wt = blockIdx.x;   // w tile 0..15
    const int h  = blockIdx.y;   // 0..511
    const int p  = blockIdx.z;   // 0..5
    const int tx = threadIdx.x;  // 0..31
    const int ty = threadIdx.y;  // 0..15

    const size_t rbase = (((size_t)p * FEAT) * RES + h) * RES + (wt * 32 + tx);
    tile[ty][tx]      = __ldcs(&planes[rbase + (size_t)ty * RES * RES]);
    tile[ty + 16][tx] = __ldcs(&planes[rbase + (size_t)(ty + 16) * RES * RES]);
    __syncthreads();

    // lane tx -> pair = tx&15, local w = ty*2 + (tx>>4)  (0..31)
    const int pair = tx & 15;
    const int wl   = ty * 2 + (tx >> 4);
    const __half2 v = __floats2half2_rn(tile[2 * pair][wl], tile[2 * pair + 1][wl]);
    const int wr = (((p * RES + h) * RES) + (wt * 32 + wl)) * PAIRS + pair;
    g_scratch[wr] = v;
}

// ---------------------------------------------------------------------------
// 8 threads per point; thread `sub` owns channels [4*sub,4*sub+4) = pairs
// 2*sub,2*sub+1. Corner fetch = 8B uint2 (aligned). fp32 interpolation.
// Output: float4 streaming stores (__stcs) so L2 keeps the scratch resident.
// ---------------------------------------------------------------------------
__global__ void __launch_bounds__(256)
sample_points_kernel(const float* __restrict__ pts,
                     const float* __restrict__ tim,
                     float* __restrict__ out,
                     int N) {
    const int g   = blockIdx.x * blockDim.x + threadIdx.x;
    const int pt  = g >> 3;
    const int sub = g & 7;
    if (pt >= N) return;

    const float inv_b = 1.0f / 1.6f;
    const float dx = pts[pt * 3 + 0] * inv_b;
    const float dy = pts[pt * 3 + 1] * inv_b;
    const float dz = pts[pt * 3 + 2] * inv_b;
    const float dt = tim[pt] * 2.0f - 1.0f;

    // idx = [[0,1],[0,2],[3,0],[1,2],[3,1],[3,2]] -> (x=W coord, y=H coord)
    const float cxs[NPLANE] = { dx, dx, dt, dy, dt, dt };
    const float cys[NPLANE] = { dy, dz, dx, dz, dy, dz };

    const __half2* __restrict__ sc = g_scratch;
    int a00[NPLANE], a01[NPLANE], a10[NPLANE], a11[NPLANE];
    float w00[NPLANE], w01[NPLANE], w10[NPLANE], w11[NPLANE];

    #pragma unroll
    for (int p = 0; p < NPLANE; ++p) {
        const float x = fminf(fmaxf((cxs[p] + 1.0f) * 0.5f * (float)(RES - 1), 0.0f), (float)(RES - 1));
        const float y = fminf(fmaxf((cys[p] + 1.0f) * 0.5f * (float)(RES - 1), 0.0f), (float)(RES - 1));
        const float x0f = floorf(x);
        const float y0f = floorf(y);
        const int x0 = (int)x0f;
        const int y0 = (int)y0f;
        const int x1 = min(x0 + 1, RES - 1);
        const int y1 = min(y0 + 1, RES - 1);
        const float wx = x - x0f;
        const float wy = y - y0f;

        const int pbase = p * (RES * RES * PAIRS) + 2 * sub;
        a00[p] = pbase + (y0 * RES + x0) * PAIRS;
        a01[p] = pbase + (y0 * RES + x1) * PAIRS;
        a10[p] = pbase + (y1 * RES + x0) * PAIRS;
        a11[p] = pbase + (y1 * RES + x1) * PAIRS;
        w00[p] = (1.0f - wx) * (1.0f - wy);
        w01[p] = wx * (1.0f - wy);
        w10[p] = (1.0f - wx) * wy;
        w11[p] = wx * wy;
    }

    uint2 c00[NPLANE], c01[NPLANE], c10[NPLANE], c11[NPLANE];
    #pragma unroll
    for (int p = 0; p < NPLANE; ++p) {
        c00[p] = __ldg((const uint2*)(sc + a00[p]));
        c01[p] = __ldg((const uint2*)(sc + a01[p]));
        c10[p] = __ldg((const uint2*)(sc + a10[p]));
        c11[p] = __ldg((const uint2*)(sc + a11[p]));
    }

    float f[NPLANE][4];
    #pragma unroll
    for (int p = 0; p < NPLANE; ++p) {
        const float2 v00a = __half22float2(*(const __half2*)&c00[p].x);
        const float2 v00b = __half22float2(*(const __half2*)&c00[p].y);
        const float2 v01a = __half22float2(*(const __half2*)&c01[p].x);
        const float2 v01b = __half22float2(*(const __half2*)&c01[p].y);
        const float2 v10a = __half22float2(*(const __half2*)&c10[p].x);
        const float2 v10b = __half22float2(*(const __half2*)&c10[p].y);
        const float2 v11a = __half22float2(*(const __half2*)&c11[p].x);
        const float2 v11b = __half22float2(*(const __half2*)&c11[p].y);

        f[p][0] = v00a.x * w00[p] + v01a.x * w01[p] + v10a.x * w10[p] + v11a.x * w11[p];
        f[p][1] = v00a.y * w00[p] + v01a.y * w01[p] + v10a.y * w10[p] + v11a.y * w11[p];
        f[p][2] = v00b.x * w00[p] + v01b.x * w01[p] + v10b.x * w10[p] + v11b.x * w11[p];
        f[p][3] = v00b.y * w00[p] + v01b.y * w01[p] + v10b.y * w10[p] + v11b.y * w11[p];
    }

    float4 space, spacetime;
    space.x = f[0][0] * f[1][0] * f[3][0];
    space.y = f[0][1] * f[1][1] * f[3][1];
    space.z = f[0][2] * f[1][2] * f[3][2];
    space.w = f[0][3] * f[1][3] * f[3][3];
    spacetime.x = f[2][0] * f[4][0] * f[5][0];
    spacetime.y = f[2][1] * f[4][1] * f[5][1];
    spacetime.z = f[2][2] * f[4][2] * f[5][2];
    spacetime.w = f[2][3] * f[4][3] * f[5][3];

    float4* __restrict__ o0 = (float4*)out + (size_t)pt * 8 + sub;
    float4* __restrict__ o1 = (float4*)out + (size_t)N * 8 + (size_t)pt * 8 + sub;
    __stcs(o0, space);
    __stcs(o1, spacetime);
}

extern "C" void kernel_launch(void* const* d_in, const int* in_sizes, int n_in,
                              void* d_out, int out_size) {
    const float* pts    = (const float*)d_in[0];
    const float* tim    = (const float*)d_in[1];
    const float* planes = (const float*)d_in[2];

    const int N = in_sizes[0] / 3;

    transpose_convert_kernel<<<dim3(RES / 32, RES, NPLANE), dim3(32, 16)>>>(planes);

    const int threads_total = N * 8;
    const int blocks = (threads_total + 255) / 256;
    sample_points_kernel<<<blocks, 256>>>(pts, tim, (float*)d_out, N);
}

// round 5
// speedup vs baseline: 2.9403x; 1.3270x over previous
#include <cuda_runtime.h>
#include <cuda_fp16.h>

#define RES    512
#define FEAT   32
#define NPLANE 6
#define PAIRS  (FEAT / 2)   // 16 half2 per texel

// Channel-last fp16 scratch: [6][512][512][16] half2 = 100.7 MB.
__device__ __half2 g_scratch[(size_t)NPLANE * RES * RES * PAIRS];

// ---------------------------------------------------------------------------
// Transpose+convert [p][c][h][w] fp32 -> [p][h][w][pair] half2.
// Block (32,16), each block handles 2 h-rows (4 reads/thread in flight).
// Write: each warp emits one 128B contiguous store per row.
// ---------------------------------------------------------------------------
__global__ void transpose_convert_kernel(const float* __restrict__ planes) {
    __shared__ float tA[32][33];
    __shared__ float tB[32][33];

    const int wt = blockIdx.x;          // w tile 0..15
    const int h0 = blockIdx.y * 2;      // 0..510
    const int h1 = h0 + 1;
    const int p  = blockIdx.z;
    const int tx = threadIdx.x;         // 0..31
    const int ty = threadIdx.y;         // 0..15

    const size_t plane_base = ((size_t)p * FEAT) * RES * RES + (wt * 32 + tx);
    const size_t cs = (size_t)RES * RES;   // channel stride

    tA[ty][tx]      = __ldcs(&planes[plane_base + (size_t)ty * cs        + (size_t)h0 * RES]);
    tA[ty + 16][tx] = __ldcs(&planes[plane_base + (size_t)(ty + 16) * cs + (size_t)h0 * RES]);
    tB[ty][tx]      = __ldcs(&planes[plane_base + (size_t)ty * cs        + (size_t)h1 * RES]);
    tB[ty + 16][tx] = __ldcs(&planes[plane_base + (size_t)(ty + 16) * cs + (size_t)h1 * RES]);
    __syncthreads();

    const int pair = tx & 15;
    const int wl   = ty * 2 + (tx >> 4);   // 0..31
    const int col  = wt * 32 + wl;

    g_scratch[(((p * RES + h0) * RES) + col) * PAIRS + pair] =
        __floats2half2_rn(tA[2 * pair][wl], tA[2 * pair + 1][wl]);
    g_scratch[(((p * RES + h1) * RES) + col) * PAIRS + pair] =
        __floats2half2_rn(tB[2 * pair][wl], tB[2 * pair + 1][wl]);
}

// ---------------------------------------------------------------------------
// Sample one product group. G=0: planes {0,1,3} -> space. G=1: planes {2,4,5}
// -> spacetime. 8 threads/point, thread sub owns channels [4sub,4sub+4).
// 12 gathers/thread, all batched for max MLP; working set = 3 planes = 50MB
// (L2-resident). Output via float4 streaming store.
// ---------------------------------------------------------------------------
template<int G>
__global__ void __launch_bounds__(256)
sample_group_kernel(const float* __restrict__ pts,
                    const float* __restrict__ tim,
                    float* __restrict__ out,
                    int N) {
    const int g   = blockIdx.x * blockDim.x + threadIdx.x;
    const int pt  = g >> 3;
    const int sub = g & 7;
    if (pt >= N) return;

    const float inv_b = 1.0f / 1.6f;
    const float dx = pts[pt * 3 + 0] * inv_b;
    const float dy = pts[pt * 3 + 1] * inv_b;
    const float dz = pts[pt * 3 + 2] * inv_b;

    float cx[3], cy[3];
    int   pid[3];
    if (G == 0) {
        // planes 0:(x,y)=(dx,dy)  1:(dx,dz)  3:(dy,dz)
        pid[0] = 0; cx[0] = dx; cy[0] = dy;
        pid[1] = 1; cx[1] = dx; cy[1] = dz;
        pid[2] = 3; cx[2] = dy; cy[2] = dz;
    } else {
        const float dt = tim[pt] * 2.0f - 1.0f;
        // planes 2:(dt,dx)  4:(dt,dy)  5:(dt,dz)
        pid[0] = 2; cx[0] = dt; cy[0] = dx;
        pid[1] = 4; cx[1] = dt; cy[1] = dy;
        pid[2] = 5; cx[2] = dt; cy[2] = dz;
    }

    const __half2* __restrict__ sc = g_scratch;
    int a00[3], a01[3], a10[3], a11[3];
    float w00[3], w01[3], w10[3], w11[3];

    #pragma unroll
    for (int i = 0; i < 3; ++i) {
        const float x = fminf(fmaxf((cx[i] + 1.0f) * 0.5f * (float)(RES - 1), 0.0f), (float)(RES - 1));
        const float y = fminf(fmaxf((cy[i] + 1.0f) * 0.5f * (float)(RES - 1), 0.0f), (float)(RES - 1));
        const float x0f = floorf(x);
        const float y0f = floorf(y);
        const int x0 = (int)x0f;
        const int y0 = (int)y0f;
        const int x1 = min(x0 + 1, RES - 1);
        const int y1 = min(y0 + 1, RES - 1);
        const float wx = x - x0f;
        const float wy = y - y0f;

        const int pbase = pid[i] * (RES * RES * PAIRS) + 2 * sub;
        a00[i] = pbase + (y0 * RES + x0) * PAIRS;
        a01[i] = pbase + (y0 * RES + x1) * PAIRS;
        a10[i] = pbase + (y1 * RES + x0) * PAIRS;
        a11[i] = pbase + (y1 * RES + x1) * PAIRS;
        w00[i] = (1.0f - wx) * (1.0f - wy);
        w01[i] = wx * (1.0f - wy);
        w10[i] = (1.0f - wx) * wy;
        w11[i] = wx * wy;
    }

    uint2 c00[3], c01[3], c10[3], c11[3];
    #pragma unroll
    for (int i = 0; i < 3; ++i) {
        c00[i] = __ldg((const uint2*)(sc + a00[i]));
        c01[i] = __ldg((const uint2*)(sc + a01[i]));
        c10[i] = __ldg((const uint2*)(sc + a10[i]));
        c11[i] = __ldg((const uint2*)(sc + a11[i]));
    }

    float f[3][4];
    #pragma unroll
    for (int i = 0; i < 3; ++i) {
        const float2 v00a = __half22float2(*(const __half2*)&c00[i].x);
        const float2 v00b = __half22float2(*(const __half2*)&c00[i].y);
        const float2 v01a = __half22float2(*(const __half2*)&c01[i].x);
        const float2 v01b = __half22float2(*(const __half2*)&c01[i].y);
        const float2 v10a = __half22float2(*(const __half2*)&c10[i].x);
        const float2 v10b = __half22float2(*(const __half2*)&c10[i].y);
        const float2 v11a = __half22float2(*(const __half2*)&c11[i].x);
        const float2 v11b = __half22float2(*(const __half2*)&c11[i].y);

        f[i][0] = v00a.x * w00[i] + v01a.x * w01[i] + v10a.x * w10[i] + v11a.x * w11[i];
        f[i][1] = v00a.y * w00[i] + v01a.y * w01[i] + v10a.y * w10[i] + v11a.y * w11[i];
        f[i][2] = v00b.x * w00[i] + v01b.x * w01[i] + v10b.x * w10[i] + v11b.x * w11[i];
        f[i][3] = v00b.y * w00[i] + v01b.y * w01[i] + v10b.y * w10[i] + v11b.y * w11[i];
    }

    float4 r;
    r.x = f[0][0] * f[1][0] * f[2][0];
    r.y = f[0][1] * f[1][1] * f[2][1];
    r.z = f[0][2] * f[1][2] * f[2][2];
    r.w = f[0][3] * f[1][3] * f[2][3];

    float4* __restrict__ o = (float4*)out + (size_t)G * N * 8 + (size_t)pt * 8 + sub;
    __stcs(o, r);
}

extern "C" void kernel_launch(void* const* d_in, const int* in_sizes, int n_in,
                              void* d_out, int out_size) {
    const float* pts    = (const float*)d_in[0];
    const float* tim    = (const float*)d_in[1];
    const float* planes = (const float*)d_in[2];

    const int N = in_sizes[0] / 3;

    transpose_convert_kernel<<<dim3(RES / 32, RES / 2, NPLANE), dim3(32, 16)>>>(planes);

    const int threads_total = N * 8;
    const int blocks = (threads_total + 255) / 256;
    sample_group_kernel<0><<<blocks, 256>>>(pts, tim, (float*)d_out, N);
    sample_group_kernel<1><<<blocks, 256>>>(pts, tim, (float*)d_out, N);
}

// round 6
// speedup vs baseline: 3.1872x; 1.0839x over previous
#include <cuda_runtime.h>
#include <cuda_fp16.h>

#define RES    512
#define FEAT   32
#define NPLANE 6
#define PAIRS  (FEAT / 2)   // 16 half2 per texel

// Channel-last fp16 scratch: [6][512][512][16] half2 = 100.7 MB.
__device__ __half2 g_scratch[(size_t)NPLANE * RES * RES * PAIRS];

// ---------------------------------------------------------------------------
// Transpose+convert [p][c][h][w] fp32 -> [p][h][w][pair] half2.
// Block (32,16), 4 h-rows per block -> 8 independent global reads in flight
// per thread. Writes: one 128B contiguous store per warp per row.
// ---------------------------------------------------------------------------
__global__ void transpose_convert_kernel(const float* __restrict__ planes) {
    __shared__ float t[4][32][33];

    const int wt = blockIdx.x;          // w tile 0..15
    const int hb = blockIdx.y * 4;      // h base
    const int p  = blockIdx.z;
    const int tx = threadIdx.x;         // 0..31
    const int ty = threadIdx.y;         // 0..15

    const size_t cs = (size_t)RES * RES;     // channel stride
    const size_t plane_base = ((size_t)p * FEAT) * cs + (wt * 32 + tx);

    #pragma unroll
    for (int r = 0; r < 4; ++r) {
        const size_t rb = plane_base + (size_t)(hb + r) * RES;
        t[r][ty][tx]      = __ldcs(&planes[rb + (size_t)ty * cs]);
        t[r][ty + 16][tx] = __ldcs(&planes[rb + (size_t)(ty + 16) * cs]);
    }
    __syncthreads();

    const int pair = tx & 15;
    const int wl   = ty * 2 + (tx >> 4);   // 0..31
    const int col  = wt * 32 + wl;

    #pragma unroll
    for (int r = 0; r < 4; ++r) {
        g_scratch[(((p * RES + (hb + r)) * RES) + col) * PAIRS + pair] =
            __floats2half2_rn(t[r][2 * pair][wl], t[r][2 * pair + 1][wl]);
    }
}

// ---------------------------------------------------------------------------
// Sample one product group; G=0: planes {0,1,3} -> space, G=1: {2,4,5} ->
// spacetime. Warp covers 8 points: lane = sub(0..7) + 8*k(0..3); each thread
// handles points wpt+k and wpt+k+4 => 24 batched 8B gathers per thread.
// Working set = 3 planes = 50MB (L2-resident). float4 streaming stores,
// 512B contiguous per warp per point-set.
// ---------------------------------------------------------------------------
template<int G>
__global__ void __launch_bounds__(256)
sample_group_kernel(const float* __restrict__ pts,
                    const float* __restrict__ tim,
                    float* __restrict__ out,
                    int N) {
    const int gwarp = (blockIdx.x * blockDim.x + threadIdx.x) >> 5;
    const int lane  = threadIdx.x & 31;
    const int sub   = lane & 7;
    const int k     = lane >> 3;

    const int wpt = gwarp * 8;
    if (wpt >= N) return;

    int ptv[2];
    ptv[0] = wpt + k;
    ptv[1] = wpt + k + 4;

    const __half2* __restrict__ sc = g_scratch;

    int   a00[2][3], a01[2][3], a10[2][3], a11[2][3];
    float w00[2][3], w01[2][3], w10[2][3], w11[2][3];
    bool  valid[2];

    #pragma unroll
    for (int q = 0; q < 2; ++q) {
        const int pt = ptv[q];
        valid[q] = (pt < N);
        const int ps = valid[q] ? pt : 0;

        const float inv_b = 1.0f / 1.6f;
        const float dx = pts[ps * 3 + 0] * inv_b;
        const float dy = pts[ps * 3 + 1] * inv_b;
        const float dz = pts[ps * 3 + 2] * inv_b;

        float cx[3], cy[3];
        int pid[3];
        if (G == 0) {
            pid[0] = 0; cx[0] = dx; cy[0] = dy;
            pid[1] = 1; cx[1] = dx; cy[1] = dz;
            pid[2] = 3; cx[2] = dy; cy[2] = dz;
        } else {
            const float dt = tim[ps] * 2.0f - 1.0f;
            pid[0] = 2; cx[0] = dt; cy[0] = dx;
            pid[1] = 4; cx[1] = dt; cy[1] = dy;
            pid[2] = 5; cx[2] = dt; cy[2] = dz;
        }

        #pragma unroll
        for (int i = 0; i < 3; ++i) {
            const float x = fminf(fmaxf((cx[i] + 1.0f) * 0.5f * (float)(RES - 1), 0.0f), (float)(RES - 1));
            const float y = fminf(fmaxf((cy[i] + 1.0f) * 0.5f * (float)(RES - 1), 0.0f), (float)(RES - 1));
            const float x0f = floorf(x);
            const float y0f = floorf(y);
            const int x0 = (int)x0f;
            const int y0 = (int)y0f;
            const int x1 = min(x0 + 1, RES - 1);
            const int y1 = min(y0 + 1, RES - 1);
            const float wx = x - x0f;
            const float wy = y - y0f;

            const int pbase = pid[i] * (RES * RES * PAIRS) + 2 * sub;
            a00[q][i] = pbase + (y0 * RES + x0) * PAIRS;
            a01[q][i] = pbase + (y0 * RES + x1) * PAIRS;
            a10[q][i] = pbase + (y1 * RES + x0) * PAIRS;
            a11[q][i] = pbase + (y1 * RES + x1) * PAIRS;
            w00[q][i] = (1.0f - wx) * (1.0f - wy);
            w01[q][i] = wx * (1.0f - wy);
            w10[q][i] = (1.0f - wx) * wy;
            w11[q][i] = wx * wy;
        }
    }

    // Issue all 24 gathers back-to-back for max MLP.
    uint2 c00[2][3], c01[2][3], c10[2][3], c11[2][3];
    #pragma unroll
    for (int q = 0; q < 2; ++q) {
        #pragma unroll
        for (int i = 0; i < 3; ++i) {
            c00[q][i] = __ldg((const uint2*)(sc + a00[q][i]));
            c01[q][i] = __ldg((const uint2*)(sc + a01[q][i]));
            c10[q][i] = __ldg((const uint2*)(sc + a10[q][i]));
            c11[q][i] = __ldg((const uint2*)(sc + a11[q][i]));
        }
    }

    #pragma unroll
    for (int q = 0; q < 2; ++q) {
        float f[3][4];
        #pragma unroll
        for (int i = 0; i < 3; ++i) {
            const float2 v00a = __half22float2(*(const __half2*)&c00[q][i].x);
            const float2 v00b = __half22float2(*(const __half2*)&c00[q][i].y);
            const float2 v01a = __half22float2(*(const __half2*)&c01[q][i].x);
            const float2 v01b = __half22float2(*(const __half2*)&c01[q][i].y);
            const float2 v10a = __half22float2(*(const __half2*)&c10[q][i].x);
            const float2 v10b = __half22float2(*(const __half2*)&c10[q][i].y);
            const float2 v11a = __half22float2(*(const __half2*)&c11[q][i].x);
            const float2 v11b = __half22float2(*(const __half2*)&c11[q][i].y);

            f[i][0] = v00a.x * w00[q][i] + v01a.x * w01[q][i] + v10a.x * w10[q][i] + v11a.x * w11[q][i];
            f[i][1] = v00a.y * w00[q][i] + v01a.y * w01[q][i] + v10a.y * w10[q][i] + v11a.y * w11[q][i];
            f[i][2] = v00b.x * w00[q][i] + v01b.x * w01[q][i] + v10b.x * w10[q][i] + v11b.x * w11[q][i];
            f[i][3] = v00b.y * w00[q][i] + v01b.y * w01[q][i] + v10b.y * w10[q][i] + v11b.y * w11[q][i];
        }

        float4 r;
        r.x = f[0][0] * f[1][0] * f[2][0];
        r.y = f[0][1] * f[1][1] * f[2][1];
        r.z = f[0][2] * f[1][2] * f[2][2];
        r.w = f[0][3] * f[1][3] * f[2][3];

        if (valid[q]) {
            float4* __restrict__ o = (float4*)out + (size_t)G * N * 8 + (size_t)ptv[q] * 8 + sub;
            __stcs(o, r);
        }
    }
}

extern "C" void kernel_launch(void* const* d_in, const int* in_sizes, int n_in,
                              void* d_out, int out_size) {
    const float* pts    = (const float*)d_in[0];
    const float* tim    = (const float*)d_in[1];
    const float* planes = (const float*)d_in[2];

    const int N = in_sizes[0] / 3;

    transpose_convert_kernel<<<dim3(RES / 32, RES / 4, NPLANE), dim3(32, 16)>>>(planes);

    // One warp per 8 points.
    const int warps  = (N + 7) / 8;
    const int blocks = (warps * 32 + 255) / 256;
    sample_group_kernel<0><<<blocks, 256>>>(pts, tim, (float*)d_out, N);
    sample_group_kernel<1><<<blocks, 256>>>(pts, tim, (float*)d_out, N);
}

// round 7
// speedup vs baseline: 3.2021x; 1.0047x over previous
#include <cuda_runtime.h>
#include <cuda_fp16.h>

#define RES    512
#define FEAT   32
#define NPLANE 6
#define PAIRS  (FEAT / 2)   // 16 half2 per texel

// Channel-last fp16 scratch: [6][512][512][16] half2 = 100.7 MB.
__device__ __half2 g_scratch[(size_t)NPLANE * RES * RES * PAIRS];

// 6144 blocks per transpose half: 16 w-tiles x 128 h-groups(4 rows) x 3 planes
#define TBLOCKS 6144

// ---------------------------------------------------------------------------
// Transpose block body: 256 threads (tx=0..31, ty=0..7), 4 h-rows, 32 chans.
// 16 independent streaming loads per thread; writes are 128B/warp contiguous.
// P0/P1/P2 select the 3 planes of this half.
// ---------------------------------------------------------------------------
template<int P0, int P1, int P2>
__device__ __forceinline__ void transpose_body(const float* __restrict__ planes,
                                               int bid) {
    __shared__ float t[4][32][33];

    const int tx = threadIdx.x & 31;
    const int ty = threadIdx.x >> 5;          // 0..7

    const int wt = bid & 15;                  // 16 w tiles
    const int hb = ((bid >> 4) & 127) * 4;    // 128 h groups of 4
    const int pj = bid >> 11;                 // 0..2
    const int p  = (pj == 0) ? P0 : (pj == 1) ? P1 : P2;

    const size_t cs = (size_t)RES * RES;
    const size_t base = ((size_t)p * FEAT) * cs + (wt * 32 + tx);

    #pragma unroll
    for (int r = 0; r < 4; ++r) {
        const size_t rb = base + (size_t)(hb + r) * RES;
        #pragma unroll
        for (int c = 0; c < 4; ++c)
            t[r][ty + 8 * c][tx] = __ldcs(&planes[rb + (size_t)(ty + 8 * c) * cs]);
    }
    __syncthreads();

    const int pair = tx & 15;
    #pragma unroll
    for (int r = 0; r < 4; ++r) {
        #pragma unroll
        for (int j = 0; j < 2; ++j) {
            const int wl  = (ty + 8 * j) * 2 + (tx >> 4);   // 0..31
            const int col = wt * 32 + wl;
            g_scratch[(((p * RES + (hb + r)) * RES) + col) * PAIRS + pair] =
                __floats2half2_rn(t[r][2 * pair][wl], t[r][2 * pair + 1][wl]);
        }
    }
}

// ---------------------------------------------------------------------------
// Sample body (as round 6): warp covers 8 points, 2 points/thread, 24 batched
// 8B gathers. G=0: planes {0,1,3} -> space half. G=1: {2,4,5} -> spacetime.
// ---------------------------------------------------------------------------
template<int G>
__device__ __forceinline__ void sample_body(const float* __restrict__ pts,
                                            const float* __restrict__ tim,
                                            float* __restrict__ out,
                                            int N, int sbid) {
    const int gwarp = (sbid * 256 + (int)threadIdx.x) >> 5;
    const int lane  = threadIdx.x & 31;
    const int sub   = lane & 7;
    const int k     = lane >> 3;

    const int wpt = gwarp * 8;
    if (wpt >= N) return;

    int ptv[2];
    ptv[0] = wpt + k;
    ptv[1] = wpt + k + 4;

    const __half2* __restrict__ sc = g_scratch;

    int   a00[2][3], a01[2][3], a10[2][3], a11[2][3];
    float w00[2][3], w01[2][3], w10[2][3], w11[2][3];
    bool  valid[2];

    #pragma unroll
    for (int q = 0; q < 2; ++q) {
        const int pt = ptv[q];
        valid[q] = (pt < N);
        const int ps = valid[q] ? pt : 0;

        const float inv_b = 1.0f / 1.6f;
        const float dx = pts[ps * 3 + 0] * inv_b;
        const float dy = pts[ps * 3 + 1] * inv_b;
        const float dz = pts[ps * 3 + 2] * inv_b;

        float cx[3], cy[3];
        int pid[3];
        if (G == 0) {
            pid[0] = 0; cx[0] = dx; cy[0] = dy;
            pid[1] = 1; cx[1] = dx; cy[1] = dz;
            pid[2] = 3; cx[2] = dy; cy[2] = dz;
        } else {
            const float dt = tim[ps] * 2.0f - 1.0f;
            pid[0] = 2; cx[0] = dt; cy[0] = dx;
            pid[1] = 4; cx[1] = dt; cy[1] = dy;
            pid[2] = 5; cx[2] = dt; cy[2] = dz;
        }

        #pragma unroll
        for (int i = 0; i < 3; ++i) {
            const float x = fminf(fmaxf((cx[i] + 1.0f) * 0.5f * (float)(RES - 1), 0.0f), (float)(RES - 1));
            const float y = fminf(fmaxf((cy[i] + 1.0f) * 0.5f * (float)(RES - 1), 0.0f), (float)(RES - 1));
            const float x0f = floorf(x);
            const float y0f = floorf(y);
            const int x0 = (int)x0f;
            const int y0 = (int)y0f;
            const int x1 = min(x0 + 1, RES - 1);
            const int y1 = min(y0 + 1, RES - 1);
            const float wx = x - x0f;
            const float wy = y - y0f;

            const int pbase = pid[i] * (RES * RES * PAIRS) + 2 * sub;
            a00[q][i] = pbase + (y0 * RES + x0) * PAIRS;
            a01[q][i] = pbase + (y0 * RES + x1) * PAIRS;
            a10[q][i] = pbase + (y1 * RES + x0) * PAIRS;
            a11[q][i] = pbase + (y1 * RES + x1) * PAIRS;
            w00[q][i] = (1.0f - wx) * (1.0f - wy);
            w01[q][i] = wx * (1.0f - wy);
            w10[q][i] = (1.0f - wx) * wy;
            w11[q][i] = wx * wy;
        }
    }

    uint2 c00[2][3], c01[2][3], c10[2][3], c11[2][3];
    #pragma unroll
    for (int q = 0; q < 2; ++q) {
        #pragma unroll
        for (int i = 0; i < 3; ++i) {
            c00[q][i] = __ldg((const uint2*)(sc + a00[q][i]));
            c01[q][i] = __ldg((const uint2*)(sc + a01[q][i]));
            c10[q][i] = __ldg((const uint2*)(sc + a10[q][i]));
            c11[q][i] = __ldg((const uint2*)(sc + a11[q][i]));
        }
    }

    #pragma unroll
    for (int q = 0; q < 2; ++q) {
        float f[3][4];
        #pragma unroll
        for (int i = 0; i < 3; ++i) {
            const float2 v00a = __half22float2(*(const __half2*)&c00[q][i].x);
            const float2 v00b = __half22float2(*(const __half2*)&c00[q][i].y);
            const float2 v01a = __half22float2(*(const __half2*)&c01[q][i].x);
            const float2 v01b = __half22float2(*(const __half2*)&c01[q][i].y);
            const float2 v10a = __half22float2(*(const __half2*)&c10[q][i].x);
            const float2 v10b = __half22float2(*(const __half2*)&c10[q][i].y);
            const float2 v11a = __half22float2(*(const __half2*)&c11[q][i].x);
            const float2 v11b = __half22float2(*(const __half2*)&c11[q][i].y);

            f[i][0] = v00a.x * w00[q][i] + v01a.x * w01[q][i] + v10a.x * w10[q][i] + v11a.x * w11[q][i];
            f[i][1] = v00a.y * w00[q][i] + v01a.y * w01[q][i] + v10a.y * w10[q][i] + v11a.y * w11[q][i];
            f[i][2] = v00b.x * w00[q][i] + v01b.x * w01[q][i] + v10b.x * w10[q][i] + v11b.x * w11[q][i];
            f[i][3] = v00b.y * w00[q][i] + v01b.y * w01[q][i] + v10b.y * w10[q][i] + v11b.y * w11[q][i];
        }

        float4 r;
        r.x = f[0][0] * f[1][0] * f[2][0];
        r.y = f[0][1] * f[1][1] * f[2][1];
        r.z = f[0][2] * f[1][2] * f[2][2];
        r.w = f[0][3] * f[1][3] * f[2][3];

        if (valid[q]) {
            float4* __restrict__ o = (float4*)out + (size_t)G * N * 8 + (size_t)ptv[q] * 8 + sub;
            __stcs(o, r);
        }
    }
}

// K1: transpose planes {0,1,3}
__global__ void __launch_bounds__(256)
transpose_first_kernel(const float* __restrict__ planes) {
    transpose_body<0, 1, 3>(planes, blockIdx.x);
}

// K2: fused — first TBLOCKS blocks transpose planes {2,4,5}; rest sample G=0.
__global__ void __launch_bounds__(256)
fused_kernel(const float* __restrict__ planes,
             const float* __restrict__ pts,
             const float* __restrict__ tim,
             float* __restrict__ out,
             int N) {
    if (blockIdx.x < TBLOCKS) {
        transpose_body<2, 4, 5>(planes, blockIdx.x);
    } else {
        sample_body<0>(pts, tim, out, N, blockIdx.x - TBLOCKS);
    }
}

// K3: sample G=1
__global__ void __launch_bounds__(256)
sample1_kernel(const float* __restrict__ pts,
               const float* __restrict__ tim,
               float* __restrict__ out,
               int N) {
    sample_body<1>(pts, tim, out, N, blockIdx.x);
}

extern "C" void kernel_launch(void* const* d_in, const int* in_sizes, int n_in,
                              void* d_out, int out_size) {
    const float* pts    = (const float*)d_in[0];
    const float* tim    = (const float*)d_in[1];
    const float* planes = (const float*)d_in[2];

    const int N = in_sizes[0] / 3;

    const int warps   = (N + 7) / 8;
    const int sblocks = (warps * 32 + 255) / 256;

    transpose_first_kernel<<<TBLOCKS, 256>>>(planes);
    fused_kernel<<<TBLOCKS + sblocks, 256>>>(planes, pts, tim, (float*)d_out, N);
    sample1_kernel<<<sblocks, 256>>>(pts, tim, (float*)d_out, N);
}

// round 8
// speedup vs baseline: 3.2718x; 1.0218x over previous
#include <cuda_runtime.h>
#include <cuda_fp16.h>

#define RES    512
#define FEAT   32
#define NPLANE 6
#define PAIRS  (FEAT / 2)   // 16 half2 per texel

// Channel-last fp16 scratch: [6][512][512][16] half2 = 100.7 MB.
__device__ __half2 g_scratch[(size_t)NPLANE * RES * RES * PAIRS];

// K1: transpose {0,1,3}, 4-row tiles: 16 wtiles x 128 hgroups x 3 = 6144 blocks
#define TB1 6144
// Fused K2: transpose {2,4,5}, 2-row tiles: 16 x 256 x 3 = 12288 blocks,
// interleaved with samplers via a mod-9 pattern (4 transpose : 5 sample).
#define TB2        12288
#define B_SPLIT    27648      // (TB2/4)*9
#define SB_PATTERN 15360      // (B_SPLIT/9)*5

// ---------------------------------------------------------------------------
// Transpose tile body: 256 threads (tx 0..31, ty 0..7), ROWS h-rows, 32 chans.
// Streaming reads coalesced in w; writes 128B contiguous per warp per row.
// ---------------------------------------------------------------------------
template<int P0, int P1, int P2, int ROWS>
__device__ __forceinline__ void transpose_body(const float* __restrict__ planes,
                                               int tb) {
    __shared__ float t[ROWS][32][33];

    const int tx = threadIdx.x & 31;
    const int ty = threadIdx.x >> 5;              // 0..7

    constexpr int HG = RES / ROWS;
    const int wt = tb & 15;
    const int hb = ((tb >> 4) % HG) * ROWS;
    const int pj = tb / (16 * HG);                // 0..2
    const int p  = (pj == 0) ? P0 : (pj == 1) ? P1 : P2;

    const size_t cs = (size_t)RES * RES;
    const size_t base = ((size_t)p * FEAT) * cs + (wt * 32 + tx);

    #pragma unroll
    for (int r = 0; r < ROWS; ++r) {
        const size_t rb = base + (size_t)(hb + r) * RES;
        #pragma unroll
        for (int c = 0; c < 4; ++c)
            t[r][ty + 8 * c][tx] = __ldcs(&planes[rb + (size_t)(ty + 8 * c) * cs]);
    }
    __syncthreads();

    const int pair = tx & 15;
    #pragma unroll
    for (int r = 0; r < ROWS; ++r) {
        #pragma unroll
        for (int j = 0; j < 2; ++j) {
            const int wl  = (ty + 8 * j) * 2 + (tx >> 4);   // 0..31
            const int col = wt * 32 + wl;
            g_scratch[(((p * RES + (hb + r)) * RES) + col) * PAIRS + pair] =
                __floats2half2_rn(t[r][2 * pair][wl], t[r][2 * pair + 1][wl]);
        }
    }
}

// ---------------------------------------------------------------------------
// Sample body: warp covers 8 points, 2 points/thread, 24 batched 8B gathers.
// G=0: planes {0,1,3} -> space. G=1: {2,4,5} -> spacetime.
// ---------------------------------------------------------------------------
template<int G>
__device__ __forceinline__ void sample_body(const float* __restrict__ pts,
                                            const float* __restrict__ tim,
                                            float* __restrict__ out,
                                            int N, int sbid) {
    const int gwarp = (sbid * 256 + (int)threadIdx.x) >> 5;
    const int lane  = threadIdx.x & 31;
    const int sub   = lane & 7;
    const int k     = lane >> 3;

    const int wpt = gwarp * 8;
    if (wpt >= N) return;

    int ptv[2];
    ptv[0] = wpt + k;
    ptv[1] = wpt + k + 4;

    const __half2* __restrict__ sc = g_scratch;

    int   a00[2][3], a01[2][3], a10[2][3], a11[2][3];
    float w00[2][3], w01[2][3], w10[2][3], w11[2][3];
    bool  valid[2];

    #pragma unroll
    for (int q = 0; q < 2; ++q) {
        const int pt = ptv[q];
        valid[q] = (pt < N);
        const int ps = valid[q] ? pt : 0;

        const float inv_b = 1.0f / 1.6f;
        const float dx = pts[ps * 3 + 0] * inv_b;
        const float dy = pts[ps * 3 + 1] * inv_b;
        const float dz = pts[ps * 3 + 2] * inv_b;

        float cx[3], cy[3];
        int pid[3];
        if (G == 0) {
            pid[0] = 0; cx[0] = dx; cy[0] = dy;
            pid[1] = 1; cx[1] = dx; cy[1] = dz;
            pid[2] = 3; cx[2] = dy; cy[2] = dz;
        } else {
            const float dt = tim[ps] * 2.0f - 1.0f;
            pid[0] = 2; cx[0] = dt; cy[0] = dx;
            pid[1] = 4; cx[1] = dt; cy[1] = dy;
            pid[2] = 5; cx[2] = dt; cy[2] = dz;
        }

        #pragma unroll
        for (int i = 0; i < 3; ++i) {
            const float x = fminf(fmaxf((cx[i] + 1.0f) * 0.5f * (float)(RES - 1), 0.0f), (float)(RES - 1));
            const float y = fminf(fmaxf((cy[i] + 1.0f) * 0.5f * (float)(RES - 1), 0.0f), (float)(RES - 1));
            const float x0f = floorf(x);
            const float y0f = floorf(y);
            const int x0 = (int)x0f;
            const int y0 = (int)y0f;
            const int x1 = min(x0 + 1, RES - 1);
            const int y1 = min(y0 + 1, RES - 1);
            const float wx = x - x0f;
            const float wy = y - y0f;

            const int pbase = pid[i] * (RES * RES * PAIRS) + 2 * sub;
            a00[q][i] = pbase + (y0 * RES + x0) * PAIRS;
            a01[q][i] = pbase + (y0 * RES + x1) * PAIRS;
            a10[q][i] = pbase + (y1 * RES + x0) * PAIRS;
            a11[q][i] = pbase + (y1 * RES + x1) * PAIRS;
            w00[q][i] = (1.0f - wx) * (1.0f - wy);
            w01[q][i] = wx * (1.0f - wy);
            w10[q][i] = (1.0f - wx) * wy;
            w11[q][i] = wx * wy;
        }
    }

    uint2 c00[2][3], c01[2][3], c10[2][3], c11[2][3];
    #pragma unroll
    for (int q = 0; q < 2; ++q) {
        #pragma unroll
        for (int i = 0; i < 3; ++i) {
            c00[q][i] = __ldg((const uint2*)(sc + a00[q][i]));
            c01[q][i] = __ldg((const uint2*)(sc + a01[q][i]));
            c10[q][i] = __ldg((const uint2*)(sc + a10[q][i]));
            c11[q][i] = __ldg((const uint2*)(sc + a11[q][i]));
        }
    }

    #pragma unroll
    for (int q = 0; q < 2; ++q) {
        float f[3][4];
        #pragma unroll
        for (int i = 0; i < 3; ++i) {
            const float2 v00a = __half22float2(*(const __half2*)&c00[q][i].x);
            const float2 v00b = __half22float2(*(const __half2*)&c00[q][i].y);
            const float2 v01a = __half22float2(*(const __half2*)&c01[q][i].x);
            const float2 v01b = __half22float2(*(const __half2*)&c01[q][i].y);
            const float2 v10a = __half22float2(*(const __half2*)&c10[q][i].x);
            const float2 v10b = __half22float2(*(const __half2*)&c10[q][i].y);
            const float2 v11a = __half22float2(*(const __half2*)&c11[q][i].x);
            const float2 v11b = __half22float2(*(const __half2*)&c11[q][i].y);

            f[i][0] = v00a.x * w00[q][i] + v01a.x * w01[q][i] + v10a.x * w10[q][i] + v11a.x * w11[q][i];
            f[i][1] = v00a.y * w00[q][i] + v01a.y * w01[q][i] + v10a.y * w10[q][i] + v11a.y * w11[q][i];
            f[i][2] = v00b.x * w00[q][i] + v01b.x * w01[q][i] + v10b.x * w10[q][i] + v11b.x * w11[q][i];
            f[i][3] = v00b.y * w00[q][i] + v01b.y * w01[q][i] + v10b.y * w10[q][i] + v11b.y * w11[q][i];
        }

        float4 r;
        r.x = f[0][0] * f[1][0] * f[2][0];
        r.y = f[0][1] * f[1][1] * f[2][1];
        r.z = f[0][2] * f[1][2] * f[2][2];
        r.w = f[0][3] * f[1][3] * f[2][3];

        if (valid[q]) {
            float4* __restrict__ o = (float4*)out + (size_t)G * N * 8 + (size_t)ptv[q] * 8 + sub;
            __stcs(o, r);
        }
    }
}

// K1: transpose planes {0,1,3}, 4-row tiles.
__global__ void __launch_bounds__(256)
transpose_first_kernel(const float* __restrict__ planes) {
    transpose_body<0, 1, 3, 4>(planes, blockIdx.x);
}

// K2: role-interleaved fused kernel.
//   bid < B_SPLIT: r=bid%9; r<4 -> transpose{2,4,5} tile (bid/9)*4+r
//                           else -> sample0 block (bid/9)*5+(r-4)
//   bid >= B_SPLIT: sample0 block SB_PATTERN + (bid - B_SPLIT)
__global__ void __launch_bounds__(256)
fused_kernel(const float* __restrict__ planes,
             const float* __restrict__ pts,
             const float* __restrict__ tim,
             float* __restrict__ out,
             int N) {
    const int bid = blockIdx.x;
    if (bid < B_SPLIT) {
        const int q = bid / 9;
        const int r = bid % 9;
        if (r < 4) {
            transpose_body<2, 4, 5, 2>(planes, q * 4 + r);
        } else {
            sample_body<0>(pts, tim, out, N, q * 5 + (r - 4));
        }
    } else {
        sample_body<0>(pts, tim, out, N, SB_PATTERN + (bid - B_SPLIT));
    }
}

// K3: sample group 1.
__global__ void __launch_bounds__(256)
sample1_kernel(const float* __restrict__ pts,
               const float* __restrict__ tim,
               float* __restrict__ out,
               int N) {
    sample_body<1>(pts, tim, out, N, blockIdx.x);
}

extern "C" void kernel_launch(void* const* d_in, const int* in_sizes, int n_in,
                              void* d_out, int out_size) {
    const float* pts    = (const float*)d_in[0];
    const float* tim    = (const float*)d_in[1];
    const float* planes = (const float*)d_in[2];

    const int N = in_sizes[0] / 3;

    const int warps   = (N + 7) / 8;
    const int sblocks = (warps * 32 + 255) / 256;

    transpose_first_kernel<<<TB1, 256>>>(planes);

    int extra = sblocks - SB_PATTERN;
    if (extra < 0) extra = 0;
    fused_kernel<<<B_SPLIT + extra, 256>>>(planes, pts, tim, (float*)d_out, N);

    sample1_kernel<<<sblocks, 256>>>(pts, tim, (float*)d_out, N);
}